// round 7
// baseline (speedup 1.0000x reference)
#include <cuda_runtime.h>

#define EPSV2    1e-8f         // EPSV^2
#define TOLSQ    9e-10f        // (3e-5)^2 relative orthogonality threshold
#define MAXSWEEP 30

// One CTA per 64x64 SPD matrix. One-sided Jacobi with REGISTER-RESIDENT
// columns. 32 teams (8 lanes each) own one pair-slot; columns live in
// registers (8 floats/lane/column). The circle tournament = fixed pairings
// + ring rotation of contents: intra-warp handoffs via shfl, warp-boundary
// handoffs via a small double-buffered shared staging area.
// R7: occupancy 4 -> 8 CTAs/SM (issue=72.7%, L1=70.7% at occ 49% -> both had
// ~30% headroom; resident warps were the binding resource).
__global__ void __launch_bounds__(256, 8)
logm_jacobi_kernel(const float* __restrict__ in, float* __restrict__ out)
{
    __shared__ __align__(16) float M[64 * 64];
    __shared__ float wlog[64];
    __shared__ int   s_flag;

    const int tid  = threadIdx.x;
    const int lane = tid & 31;
    const int warp = tid >> 5;
    const int team = lane >> 3;               // 4 teams per warp
    const int sl   = lane & 7;                // lane within team
    const unsigned tm = 0xffu << (team << 3); // team shfl mask
    const int k = warp * 4 + team;            // slot 0..31
    const bool slot0  = (k == 0);
    const bool slot31 = (k == 31);
    const size_t base = (size_t)blockIdx.x * 4096;

    // ---- load: slot k holds columns k (top) and 32+k (bottom) ----
    float T[8], B[8];
    {
        const float4* gt = reinterpret_cast<const float4*>(in + base + k * 64 + sl * 8);
        const float4* gb = reinterpret_cast<const float4*>(in + base + (32 + k) * 64 + sl * 8);
        float4 t0 = gt[0], t1 = gt[1], b0 = gb[0], b1 = gb[1];
        T[0]=t0.x; T[1]=t0.y; T[2]=t0.z; T[3]=t0.w;
        T[4]=t1.x; T[5]=t1.y; T[6]=t1.z; T[7]=t1.w;
        B[0]=b0.x; B[1]=b0.y; B[2]=b0.z; B[3]=b0.w;
        B[4]=b1.x; B[5]=b1.y; B[6]=b1.z; B[7]=b1.w;
    }

    // ---- one-sided Jacobi sweeps ----
    for (int sweep = 0; sweep < MAXSWEEP; ++sweep) {
        if (tid == 0) s_flag = 0;
        __syncthreads();

        for (int r = 0; r < 63; ++r) {
            // --- pair visit: all in registers ---
            float dpq = 0.f, dpp = 0.f, dqq = 0.f;
            #pragma unroll
            for (int i = 0; i < 8; ++i) {
                dpq = fmaf(T[i], B[i], dpq);
                dpp = fmaf(T[i], T[i], dpp);
                dqq = fmaf(B[i], B[i], dqq);
            }
            #pragma unroll
            for (int o = 4; o; o >>= 1) {
                dpq += __shfl_xor_sync(tm, dpq, o);
                dpp += __shfl_xor_sync(tm, dpp, o);
                dqq += __shfl_xor_sync(tm, dqq, o);
            }

            if (dpq * dpq > TOLSQ * dpp * dqq) {   // shfl-free branch body
                float tau = __fdividef(dqq - dpp, 2.0f * dpq);
                float t = copysignf(1.0f, tau) /
                          (fabsf(tau) + sqrtf(1.0f + tau * tau));
                float c = rsqrtf(1.0f + t * t);
                float s = t * c;
                #pragma unroll
                for (int i = 0; i < 8; ++i) {
                    float tp = c * T[i] - s * B[i];
                    B[i]     = s * T[i] + c * B[i];
                    T[i]     = tp;
                }
                if (sl == 0) s_flag = 1;
            }

            // --- ring exchange: T shifts +1 slot, B shifts -1 slot,
            //     slot0.top fixed, slot0.bot -> slot1.top, slot31.top -> slot31.bot ---
            const int par = r & 1;
            float* stT = M + par * 512;           // staged T for dest warp w
            float* stB = M + 1024 + par * 512;    // staged B for dest warp w
            if (team == 3 && warp < 7) {          // T crosses warp boundary ->
                float4* d = reinterpret_cast<float4*>(stT + (warp + 1) * 64 + sl * 8);
                d[0] = make_float4(T[0], T[1], T[2], T[3]);
                d[1] = make_float4(T[4], T[5], T[6], T[7]);
            }
            if (team == 0 && warp > 0) {          // B crosses warp boundary <-
                float4* d = reinterpret_cast<float4*>(stB + (warp - 1) * 64 + sl * 8);
                d[0] = make_float4(B[0], B[1], B[2], B[3]);
                d[1] = make_float4(B[4], B[5], B[6], B[7]);
            }
            __syncthreads();

            // unconditional shfls (all 32 lanes), predicated selects after
            #pragma unroll
            for (int i = 0; i < 8; ++i) {
                float contrib = slot0 ? B[i] : T[i];   // slot0 passes its B up
                float oldT = T[i];
                float u = __shfl_up_sync(0xffffffffu, contrib, 8);
                float d = __shfl_down_sync(0xffffffffu, B[i], 8);
                T[i] = slot0  ? oldT : u;              // slot0 top fixed
                B[i] = slot31 ? oldT : d;              // slot31: top -> bottom
            }
            if (team == 0 && warp > 0) {               // receive T from warp-1
                const float4* s4 = reinterpret_cast<const float4*>(stT + warp * 64 + sl * 8);
                float4 a = s4[0], b = s4[1];
                T[0]=a.x; T[1]=a.y; T[2]=a.z; T[3]=a.w;
                T[4]=b.x; T[5]=b.y; T[6]=b.z; T[7]=b.w;
            }
            if (team == 3 && warp < 7) {               // receive B from warp+1
                const float4* s4 = reinterpret_cast<const float4*>(stB + warp * 64 + sl * 8);
                float4 a = s4[0], b = s4[1];
                B[0]=a.x; B[1]=a.y; B[2]=a.z; B[3]=a.w;
                B[4]=b.x; B[5]=b.y; B[6]=b.z; B[7]=b.w;
            }
        }

        int active = s_flag;
        __syncthreads();          // everyone reads flag before next reset;
        if (!active) break;       // also fences last round's staging reads
    }

    // ---- norms -> eigenvalues; normalized columns -> M (order-free) ----
    {
        float dpp = 0.f, dqq = 0.f;
        #pragma unroll
        for (int i = 0; i < 8; ++i) {
            dpp = fmaf(T[i], T[i], dpp);
            dqq = fmaf(B[i], B[i], dqq);
        }
        #pragma unroll
        for (int o = 4; o; o >>= 1) {
            dpp += __shfl_xor_sync(tm, dpp, o);
            dqq += __shfl_xor_sync(tm, dqq, o);
        }
        float it = (dpp > 1e-30f) ? rsqrtf(dpp) : 0.0f;
        float ib = (dqq > 1e-30f) ? rsqrtf(dqq) : 0.0f;
        float4* mt = reinterpret_cast<float4*>(M + (2 * k) * 64 + sl * 8);
        float4* mb = reinterpret_cast<float4*>(M + (2 * k + 1) * 64 + sl * 8);
        mt[0] = make_float4(T[0]*it, T[1]*it, T[2]*it, T[3]*it);
        mt[1] = make_float4(T[4]*it, T[5]*it, T[6]*it, T[7]*it);
        mb[0] = make_float4(B[0]*ib, B[1]*ib, B[2]*ib, B[3]*ib);
        mb[1] = make_float4(B[4]*ib, B[5]*ib, B[6]*ib, B[7]*ib);
        if (sl == 0) {
            wlog[2 * k]     = 0.5f * logf(fmaxf(dpp, EPSV2));
            wlog[2 * k + 1] = 0.5f * logf(fmaxf(dqq, EPSV2));
        }
    }
    __syncthreads();

    // ---- O = U diag(w) U^T, 4x4 register tile per thread ----
    const int ta = tid >> 4;
    const int tb = tid & 15;
    float acc[4][4];
    #pragma unroll
    for (int i = 0; i < 4; ++i)
        #pragma unroll
        for (int j = 0; j < 4; ++j) acc[i][j] = 0.0f;

    for (int kk = 0; kk < 64; ++kk) {
        float w = wlog[kk];
        float4 ur = *reinterpret_cast<const float4*>(M + kk * 64 + 4 * ta);
        float4 uc = *reinterpret_cast<const float4*>(M + kk * 64 + 4 * tb);
        float r0 = w * ur.x, r1 = w * ur.y, r2 = w * ur.z, r3 = w * ur.w;
        acc[0][0] += r0 * uc.x; acc[0][1] += r0 * uc.y; acc[0][2] += r0 * uc.z; acc[0][3] += r0 * uc.w;
        acc[1][0] += r1 * uc.x; acc[1][1] += r1 * uc.y; acc[1][2] += r1 * uc.z; acc[1][3] += r1 * uc.w;
        acc[2][0] += r2 * uc.x; acc[2][1] += r2 * uc.y; acc[2][2] += r2 * uc.z; acc[2][3] += r2 * uc.w;
        acc[3][0] += r3 * uc.x; acc[3][1] += r3 * uc.y; acc[3][2] += r3 * uc.z; acc[3][3] += r3 * uc.w;
    }

    float* go = out + base;
    #pragma unroll
    for (int i = 0; i < 4; ++i) {
        float4 v = make_float4(acc[i][0], acc[i][1], acc[i][2], acc[i][3]);
        *reinterpret_cast<float4*>(go + (4 * ta + i) * 64 + 4 * tb) = v;
    }
}

extern "C" void kernel_launch(void* const* d_in, const int* in_sizes, int n_in,
                              void* d_out, int out_size)
{
    const float* x = (const float*)d_in[0];
    float* out = (float*)d_out;
    int batches = in_sizes[0] / 4096;
    logm_jacobi_kernel<<<batches, 256>>>(x, out);
}

// round 8
// speedup vs baseline: 1.4512x; 1.4512x over previous
#include <cuda_runtime.h>

#define EPSV2    1e-8f         // EPSV^2
#define TOLSQ    9e-10f        // (3e-5)^2 relative orthogonality threshold
#define MAXSWEEP 30
#define FULLM    0xffffffffu

// One CTA per 64x64 SPD matrix. One-sided Jacobi, register-resident columns,
// HIERARCHICAL tournament:
//   - 16 half-blocks of 4 columns; warp w holds two of them (TH, BH) as
//     T[8]/B[8] per lane (team t of warp owns column t of each half-block).
//   - inner: 4 cross rounds per outer round, pairing (tc_t, bc_{t+rho}) via a
//     full-warp rotate shfl of B. No barrier, no staging.
//   - outer: 15 rounds/sweep; half-blocks move through the R6-validated ring
//     (TH +1 warp, BH -1 warp, warp0 TH fixed, warp7 TH->BH) via parity
//     double-buffered smem staging. ONE barrier per outer round (vs 63/sweep).
//   - intra-half pairs (6 per half-block) once per sweep: 3-round
//     mini-tournament after shfl gathers.
// All shfls unconditional (R3 deadlock lesson). Rotation branch = FMA only.
__global__ void __launch_bounds__(256, 4)
logm_jacobi_kernel(const float* __restrict__ in, float* __restrict__ out)
{
    // SH: staging during sweeps ([parity][T/B][warp][256] = 8192 floats);
    //     reused as the U matrix (4096 floats) for the epilogue.
    __shared__ __align__(16) float SH[8192];
    __shared__ float wlog[64];
    __shared__ int   s_flag;

    const int tid  = threadIdx.x;
    const int lane = tid & 31;
    const int warp = tid >> 5;
    const int team = lane >> 3;               // 4 teams per warp
    const int sl   = lane & 7;                // lane within team
    const unsigned tm = 0xffu << (team << 3); // team shfl mask
    const size_t base = (size_t)blockIdx.x * 4096;

    // pair visit: 3 exact dots + team butterfly + (team-uniform) rotation
#define VISIT(TT, BB)                                                        \
    {                                                                        \
        float dpq = 0.f, dpp = 0.f, dqq = 0.f;                               \
        _Pragma("unroll")                                                    \
        for (int i = 0; i < 8; ++i) {                                        \
            dpq = fmaf(TT[i], BB[i], dpq);                                   \
            dpp = fmaf(TT[i], TT[i], dpp);                                   \
            dqq = fmaf(BB[i], BB[i], dqq);                                   \
        }                                                                    \
        _Pragma("unroll")                                                    \
        for (int o = 4; o; o >>= 1) {                                        \
            dpq += __shfl_xor_sync(tm, dpq, o);                              \
            dpp += __shfl_xor_sync(tm, dpp, o);                              \
            dqq += __shfl_xor_sync(tm, dqq, o);                              \
        }                                                                    \
        if (dpq * dpq > TOLSQ * dpp * dqq) {                                 \
            float tau = __fdividef(dqq - dpp, 2.0f * dpq);                   \
            float t = copysignf(1.0f, tau) /                                 \
                      (fabsf(tau) + sqrtf(1.0f + tau * tau));                \
            float c = rsqrtf(1.0f + t * t);                                  \
            float s = t * c;                                                 \
            _Pragma("unroll")                                                \
            for (int i = 0; i < 8; ++i) {                                    \
                float tp = c * TT[i] - s * BB[i];                            \
                BB[i]    = s * TT[i] + c * BB[i];                            \
                TT[i]    = tp;                                               \
            }                                                                \
            if (sl == 0) s_flag = 1;                                         \
        }                                                                    \
    }

    // ---- load: warp w team t holds cols 4w+t (T) and 32+4w+t (B) ----
    float T[8], B[8];
    {
        const int c = warp * 4 + team;
        const float4* gt = reinterpret_cast<const float4*>(in + base + c * 64 + sl * 8);
        const float4* gb = reinterpret_cast<const float4*>(in + base + (32 + c) * 64 + sl * 8);
        float4 t0 = gt[0], t1 = gt[1], b0 = gb[0], b1 = gb[1];
        T[0]=t0.x; T[1]=t0.y; T[2]=t0.z; T[3]=t0.w;
        T[4]=t1.x; T[5]=t1.y; T[6]=t1.z; T[7]=t1.w;
        B[0]=b0.x; B[1]=b0.y; B[2]=b0.z; B[3]=b0.w;
        B[4]=b1.x; B[5]=b1.y; B[6]=b1.z; B[7]=b1.w;
    }

    const int rotsrc = (lane + 8) & 31;       // +1-team rotation source

    for (int sweep = 0; sweep < MAXSWEEP; ++sweep) {
        if (tid == 0) s_flag = 0;
        __syncthreads();

        for (int outer = 0; outer < 15; ++outer) {
            // ---- 4 inner cross rounds (intra-warp only) ----
            #pragma unroll
            for (int rho = 0; rho < 4; ++rho) {
                VISIT(T, B);
                #pragma unroll
                for (int i = 0; i < 8; ++i)      // rotate B one team; 4 rots = identity
                    B[i] = __shfl_sync(FULLM, B[i], rotsrc);
            }

            // ---- intra-half pairs, once per sweep ----
            if (outer == 0) {
                // gather: t0:(tc0,tc1) t1:(tc2,tc3) t2:(bc0,bc1) t3:(bc2,bc3)
                const int sTA = (team == 1) ? rotsrc : lane;              // newT src in T (teams 0,1)
                const int sBA = (team == 2) ? ((lane + 16) & 31) : ((lane + 24) & 31); // newT src in B (2,3)
                const int sTB = (team == 0) ? rotsrc : ((lane + 16) & 31);// newB src in T (0,1)
                const int sBB = (team == 2) ? ((lane + 24) & 31) : lane;  // newB src in B (2,3)
                #pragma unroll
                for (int i = 0; i < 8; ++i) {
                    float tA = __shfl_sync(FULLM, T[i], sTA);
                    float bA = __shfl_sync(FULLM, B[i], sBA);
                    float tB = __shfl_sync(FULLM, T[i], sTB);
                    float bB = __shfl_sync(FULLM, B[i], sBB);
                    T[i] = (team < 2) ? tA : bA;
                    B[i] = (team < 2) ? tB : bB;
                }
                VISIT(T, B);
                {   // swap1: even.B <-> odd.T (xor 8)
                    const bool ev = ((team & 1) == 0);
                    #pragma unroll
                    for (int i = 0; i < 8; ++i) {
                        float tx = __shfl_xor_sync(FULLM, T[i], 8);
                        float bx = __shfl_xor_sync(FULLM, B[i], 8);
                        float nB = ev ? tx : B[i];
                        float nT = ev ? T[i] : bx;
                        T[i] = nT; B[i] = nB;
                    }
                }
                VISIT(T, B);
                #pragma unroll
                for (int i = 0; i < 8; ++i)      // swap2: B <-> B (xor 8)
                    B[i] = __shfl_xor_sync(FULLM, B[i], 8);
                VISIT(T, B);
                // restore home: t:(tc_t, bc_t)
                const int rT = (team == 2) ? ((lane + 24) & 31) : rotsrc;       // B src for newT (2,3)
                const int rB = (team == 2) ? rotsrc : ((lane + 24) & 31);       // B src for newB (2,3)
                const int r16 = (lane + 16) & 31;
                #pragma unroll
                for (int i = 0; i < 8; ++i) {
                    float rb  = __shfl_sync(FULLM, B[i], rT);
                    float rt  = __shfl_sync(FULLM, T[i], r16);
                    float rb2 = __shfl_sync(FULLM, B[i], rB);
                    T[i] = (team < 2) ? T[i] : rb;
                    B[i] = (team < 2) ? rt   : rb2;
                }
            }

            // ---- outer rotation: half-blocks through the ring via staging ----
            float* st  = SH + (outer & 1) * 4096;
            float* stT = st;                       // [warp][256]
            float* stB = st + 2048;
            const int off = team * 64 + sl * 8;
            if (warp >= 1 && warp <= 6) {          // TH -> warp+1
                float4* d = reinterpret_cast<float4*>(stT + (warp + 1) * 256 + off);
                d[0] = make_float4(T[0], T[1], T[2], T[3]);
                d[1] = make_float4(T[4], T[5], T[6], T[7]);
            }
            if (warp == 0) {                       // BH_0 -> warp1's TH
                float4* d = reinterpret_cast<float4*>(stT + 1 * 256 + off);
                d[0] = make_float4(B[0], B[1], B[2], B[3]);
                d[1] = make_float4(B[4], B[5], B[6], B[7]);
            }
            if (warp >= 1) {                       // BH -> warp-1
                float4* d = reinterpret_cast<float4*>(stB + (warp - 1) * 256 + off);
                d[0] = make_float4(B[0], B[1], B[2], B[3]);
                d[1] = make_float4(B[4], B[5], B[6], B[7]);
            }
            if (warp == 7) {                       // TH_7 -> own BH (after B staged)
                #pragma unroll
                for (int i = 0; i < 8; ++i) B[i] = T[i];
            }
            __syncthreads();
            if (warp >= 1) {                       // receive TH
                const float4* s4 = reinterpret_cast<const float4*>(stT + warp * 256 + off);
                float4 a = s4[0], b = s4[1];
                T[0]=a.x; T[1]=a.y; T[2]=a.z; T[3]=a.w;
                T[4]=b.x; T[5]=b.y; T[6]=b.z; T[7]=b.w;
            }
            if (warp <= 6) {                       // receive BH
                const float4* s4 = reinterpret_cast<const float4*>(stB + warp * 256 + off);
                float4 a = s4[0], b = s4[1];
                B[0]=a.x; B[1]=a.y; B[2]=a.z; B[3]=a.w;
                B[4]=b.x; B[5]=b.y; B[6]=b.z; B[7]=b.w;
            }
        }

        int active = s_flag;
        __syncthreads();          // fences last parity-0 reads vs next sweep's writes
        if (!active) break;
    }

    // ---- norms -> eigenvalues; normalized columns -> SH (order-free) ----
    {
        const int k = warp * 4 + team;
        float dpp = 0.f, dqq = 0.f;
        #pragma unroll
        for (int i = 0; i < 8; ++i) {
            dpp = fmaf(T[i], T[i], dpp);
            dqq = fmaf(B[i], B[i], dqq);
        }
        #pragma unroll
        for (int o = 4; o; o >>= 1) {
            dpp += __shfl_xor_sync(tm, dpp, o);
            dqq += __shfl_xor_sync(tm, dqq, o);
        }
        float it = (dpp > 1e-30f) ? rsqrtf(dpp) : 0.0f;
        float ib = (dqq > 1e-30f) ? rsqrtf(dqq) : 0.0f;
        float4* mt = reinterpret_cast<float4*>(SH + (2 * k) * 64 + sl * 8);
        float4* mb = reinterpret_cast<float4*>(SH + (2 * k + 1) * 64 + sl * 8);
        mt[0] = make_float4(T[0]*it, T[1]*it, T[2]*it, T[3]*it);
        mt[1] = make_float4(T[4]*it, T[5]*it, T[6]*it, T[7]*it);
        mb[0] = make_float4(B[0]*ib, B[1]*ib, B[2]*ib, B[3]*ib);
        mb[1] = make_float4(B[4]*ib, B[5]*ib, B[6]*ib, B[7]*ib);
        if (sl == 0) {
            wlog[2 * k]     = 0.5f * logf(fmaxf(dpp, EPSV2));
            wlog[2 * k + 1] = 0.5f * logf(fmaxf(dqq, EPSV2));
        }
    }
    __syncthreads();

    // ---- O = U diag(w) U^T, 4x4 register tile per thread ----
    const int ta = tid >> 4;
    const int tb = tid & 15;
    float acc[4][4];
    #pragma unroll
    for (int i = 0; i < 4; ++i)
        #pragma unroll
        for (int j = 0; j < 4; ++j) acc[i][j] = 0.0f;

    for (int kk = 0; kk < 64; ++kk) {
        float w = wlog[kk];
        float4 ur = *reinterpret_cast<const float4*>(SH + kk * 64 + 4 * ta);
        float4 uc = *reinterpret_cast<const float4*>(SH + kk * 64 + 4 * tb);
        float r0 = w * ur.x, r1 = w * ur.y, r2 = w * ur.z, r3 = w * ur.w;
        acc[0][0] += r0 * uc.x; acc[0][1] += r0 * uc.y; acc[0][2] += r0 * uc.z; acc[0][3] += r0 * uc.w;
        acc[1][0] += r1 * uc.x; acc[1][1] += r1 * uc.y; acc[1][2] += r1 * uc.z; acc[1][3] += r1 * uc.w;
        acc[2][0] += r2 * uc.x; acc[2][1] += r2 * uc.y; acc[2][2] += r2 * uc.z; acc[2][3] += r2 * uc.w;
        acc[3][0] += r3 * uc.x; acc[3][1] += r3 * uc.y; acc[3][2] += r3 * uc.z; acc[3][3] += r3 * uc.w;
    }

    float* go = out + base;
    #pragma unroll
    for (int i = 0; i < 4; ++i) {
        float4 v = make_float4(acc[i][0], acc[i][1], acc[i][2], acc[i][3]);
        *reinterpret_cast<float4*>(go + (4 * ta + i) * 64 + 4 * tb) = v;
    }
#undef VISIT
}

extern "C" void kernel_launch(void* const* d_in, const int* in_sizes, int n_in,
                              void* d_out, int out_size)
{
    const float* x = (const float*)d_in[0];
    float* out = (float*)d_out;
    int batches = in_sizes[0] / 4096;
    logm_jacobi_kernel<<<batches, 256>>>(x, out);
}